// round 7
// baseline (speedup 1.0000x reference)
#include <cuda_runtime.h>

#define BATCH 4
#define NPT   8192
#define KNB   9
#define CH    7
#define NPTS  (BATCH*NPT)      // 32768
#define NROWS (NPTS*KNB)       // 294912
#define SLICES 4
#define SLICE_N (NPT/SLICES)   // 2048

// ---------------- device scratch (no allocations allowed) ----------------
__device__ float  g_pd[NPTS*SLICES*KNB];    // partial top-9 distances (sorted asc)
__device__ int    g_pi[NPTS*SLICES*KNB];    // partial top-9 indices
__device__ float4 g_h[NROWS*2];             // hidden activations, 8 floats/row (padded)
__device__ float  g_sum1[CH], g_sq1[CH];    // BN1 accumulators (zero-init, re-zeroed each launch)
__device__ float  g_sum2[CH], g_sq2[CH];    // BN2 accumulators
__device__ float  g_aff1[2*CH];             // [scale..., shift...]
__device__ float  g_aff2[2*CH];

#define INF_F (__int_as_float(0x7f800000))

typedef unsigned long long ull;

__device__ __forceinline__ ull pk2(float a, float b) {
    return (ull)__float_as_uint(a) | ((ull)__float_as_uint(b) << 32);
}
__device__ __forceinline__ float2 upk2(ull v) {
    float2 r;
    r.x = __uint_as_float((unsigned)(v & 0xffffffffull));
    r.y = __uint_as_float((unsigned)(v >> 32));
    return r;
}
__device__ __forceinline__ ull fma2(ull a, ull b, ull c) {
    ull d;
    asm("fma.rn.f32x2 %0, %1, %2, %3;" : "=l"(d) : "l"(a), "l"(b), "l"(c));
    return d;
}

// ---------------- kernel 1: sliced brute-force 9-NN ----------------
// block: 256 queries x one candidate slice (SLICE_N candidates in smem, packed pairs)
__global__ void __launch_bounds__(256) knn_kernel(const float* __restrict__ x) {
    extern __shared__ ulonglong2 spk[];     // [SLICE_N] : pair p -> spk[2p]={x01,y01}, spk[2p+1]={z01,w01}
    const int b = blockIdx.y;
    const int s = blockIdx.z;
    const int sbase = s * SLICE_N;
    const float* xb = x + b * (NPT * 3);

    for (int p = threadIdx.x; p < SLICE_N / 2; p += 256) {
        const int c0 = sbase + 2 * p, c1 = c0 + 1;
        float x0 = xb[3*c0], y0 = xb[3*c0+1], z0 = xb[3*c0+2];
        float x1 = xb[3*c1], y1 = xb[3*c1+1], z1 = xb[3*c1+2];
        float w0 = fmaf(x0, x0, fmaf(y0, y0, z0 * z0));
        float w1 = fmaf(x1, x1, fmaf(y1, y1, z1 * z1));
        ulonglong2 A, B;
        A.x = pk2(x0, x1); A.y = pk2(y0, y1);
        B.x = pk2(z0, z1); B.y = pk2(w0, w1);
        spk[2*p]     = A;
        spk[2*p + 1] = B;
    }
    __syncthreads();

    const int n = blockIdx.x * 256 + threadIdx.x;   // query within batch
    const float qx = xb[3*n], qy = xb[3*n+1], qz = xb[3*n+2];
    const float ax = -2.0f * qx, ay = -2.0f * qy, az = -2.0f * qz;
    const ull axx = pk2(ax, ax), ayy = pk2(ay, ay), azz = pk2(az, az);

    float dist[KNB]; int idn[KNB];
#pragma unroll
    for (int j = 0; j < KNB; ++j) { dist[j] = INF_F; idn[j] = 0; }
    float thr = INF_F;

    for (int pp = 0; pp < SLICE_N / 2; pp += 4) {       // 8 candidates per group
        ull d01[4];
#pragma unroll
        for (int i = 0; i < 4; ++i) {
            ulonglong2 A = spk[2*(pp + i)];
            ulonglong2 B = spk[2*(pp + i) + 1];
            // same FMA order as scalar: fmaf(x,ax, fmaf(y,ay, fmaf(z,az,w)))
            ull t = fma2(B.x, azz, B.y);
            t = fma2(A.y, ayy, t);
            d01[i] = fma2(A.x, axx, t);
        }
        float2 f0 = upk2(d01[0]), f1 = upk2(d01[1]), f2 = upk2(d01[2]), f3 = upk2(d01[3]);
        float gmin = fminf(fminf(fminf(f0.x, f0.y), fminf(f1.x, f1.y)),
                           fminf(fminf(f2.x, f2.y), fminf(f3.x, f3.y)));
        if (gmin < thr) {
#pragma unroll
            for (int i = 0; i < 4; ++i) {
                float2 f = upk2(d01[i]);
#pragma unroll
                for (int h = 0; h < 2; ++h) {
                    float dd = h ? f.y : f.x;
                    int mm = sbase + 2 * (pp + i) + h;
                    if (dd < thr && mm != n) {
                        dist[KNB-1] = dd; idn[KNB-1] = mm;
#pragma unroll
                        for (int j = KNB-1; j > 0; --j) {
                            if (dist[j] < dist[j-1]) {
                                float td = dist[j]; dist[j] = dist[j-1]; dist[j-1] = td;
                                int   ti = idn[j];  idn[j]  = idn[j-1];  idn[j-1]  = ti;
                            }
                        }
                        thr = dist[KNB-1];
                    }
                }
            }
        }
    }

    const int q = b * NPT + n;
    const int pb = (q * SLICES + s) * KNB;
#pragma unroll
    for (int j = 0; j < KNB; ++j) { g_pd[pb + j] = dist[j]; g_pi[pb + j] = idn[j]; }
}

// ---------------- merge two sorted 9-lists (left list has lower indices; ties -> left,
// matching top_k's lower-index-first ordering) ----------------
__device__ __forceinline__ void merge2(const float* da, const int* ia,
                                       const float* db, const int* ib,
                                       float* dc, int* ic) {
    int a = 0, c = 0;
#pragma unroll
    for (int j = 0; j < KNB; ++j) {
        bool ta = (da[a] <= db[c]);
        dc[j] = ta ? da[a] : db[c];
        ic[j] = ta ? ia[a] : ib[c];
        a += ta ? 1 : 0;
        c += ta ? 0 : 1;
    }
}

// ---------------- block reduction of 14 partial sums -> global atomics ----------------
__device__ __forceinline__ void block_reduce_14(float* v, float* dst1, float* dst2) {
    __shared__ float red[8 * 14];
    const int lane = threadIdx.x & 31, w = threadIdx.x >> 5;
#pragma unroll
    for (int i = 0; i < 14; ++i) {
        float t = v[i];
        t += __shfl_down_sync(0xffffffffu, t, 16);
        t += __shfl_down_sync(0xffffffffu, t, 8);
        t += __shfl_down_sync(0xffffffffu, t, 4);
        t += __shfl_down_sync(0xffffffffu, t, 2);
        t += __shfl_down_sync(0xffffffffu, t, 1);
        v[i] = t;
    }
    if (lane == 0) {
#pragma unroll
        for (int i = 0; i < 14; ++i) red[w * 14 + i] = v[i];
    }
    __syncthreads();
    if (threadIdx.x < 14) {
        float t = 0.f;
#pragma unroll
        for (int ww = 0; ww < 8; ++ww) t += red[ww * 14 + threadIdx.x];
        if (threadIdx.x < CH) atomicAdd(&dst1[threadIdx.x], t);
        else                  atomicAdd(&dst2[threadIdx.x - CH], t);
    }
}

// ---------------- kernel 2: 4-way merge + features + MLP1 + BN1 stats ----------------
__global__ void __launch_bounds__(256) feat_kernel(const float* __restrict__ x,
                                                   const float* __restrict__ w1) {
    __shared__ float w1s[CH * CH];
    if (threadIdx.x < CH * CH) w1s[threadIdx.x] = w1[threadIdx.x];
    __syncthreads();

    const int p = blockIdx.x * 256 + threadIdx.x;     // 0..NPTS-1
    const int b = p >> 13;
    const int n = p & (NPT - 1);

    // --- merge the 4 sorted partial top-9 lists (register-resident) ---
    float d0[KNB], d1[KNB], d2[KNB], d3[KNB];
    int   i0[KNB], i1[KNB], i2[KNB], i3[KNB];
    const int pb = p * SLICES * KNB;
#pragma unroll
    for (int j = 0; j < KNB; ++j) {
        d0[j] = g_pd[pb + 0*KNB + j]; i0[j] = g_pi[pb + 0*KNB + j];
        d1[j] = g_pd[pb + 1*KNB + j]; i1[j] = g_pi[pb + 1*KNB + j];
        d2[j] = g_pd[pb + 2*KNB + j]; i2[j] = g_pi[pb + 2*KNB + j];
        d3[j] = g_pd[pb + 3*KNB + j]; i3[j] = g_pi[pb + 3*KNB + j];
    }
    float dA[KNB], dB[KNB], dF[KNB]; int iA[KNB], iB[KNB], iF[KNB];
    merge2(d0, i0, d1, i1, dA, iA);
    merge2(d2, i2, d3, i3, dB, iB);
    merge2(dA, iA, dB, iB, dF, iF);

    const float* xb = x + b * (NPT * 3);
    const float qx = xb[3*n], qy = xb[3*n+1], qz = xb[3*n+2];

    float vx[KNB], vy[KNB], vz[KNB], ph[KNB];
#pragma unroll
    for (int j = 0; j < KNB; ++j) {
        int mi = iF[j];
        vx[j] = xb[3*mi]   - qx;
        vy[j] = xb[3*mi+1] - qy;
        vz[j] = xb[3*mi+2] - qz;
        ph[j] = atan2f(vy[j], vx[j]);   // monotone in reference's phi
    }
    // stable unrolled insertion sort by phi ascending (registers only)
#pragma unroll
    for (int i = 1; i < KNB; ++i)
#pragma unroll
        for (int j = i; j > 0; --j)
            if (ph[j] < ph[j-1]) {
                float t;
                t = ph[j]; ph[j] = ph[j-1]; ph[j-1] = t;
                t = vx[j]; vx[j] = vx[j-1]; vx[j-1] = t;
                t = vy[j]; vy[j] = vy[j-1]; vy[j-1] = t;
                t = vz[j]; vz[j] = vz[j-1]; vz[j-1] = t;
            }

    float mask = 1.0f;
    float vals[2 * CH];
#pragma unroll
    for (int i = 0; i < 2 * CH; ++i) vals[i] = 0.f;

#pragma unroll
    for (int j = 0; j < KNB; ++j) {
        const int j2 = (j + 1 == KNB) ? 0 : (j + 1);
        float axv = vx[j],  ayv = vy[j],  azv = vz[j];
        float bxv = vx[j2], byv = vy[j2], bzv = vz[j2];
        float cx = 0.5f * (axv + bxv), cy = 0.5f * (ayv + byv), cz = 0.5f * (azv + bzv);
        float nx = fmaf(ayv, bzv, -azv * byv) + 1e-5f;
        float ny = fmaf(azv, bxv, -axv * bzv) + 1e-5f;
        float nz = fmaf(axv, byv, -ayv * bxv) + 1e-5f;
        float inv = rsqrtf(fmaf(nx, nx, fmaf(ny, ny, nz * nz)));
        nx *= inv; ny *= inv; nz *= inv;
        if (j == 0) mask = (nx > 0.f) ? 1.f : -1.f;
        nx *= mask; ny *= mask; nz *= mask;
        float pos = fmaf(cx, nx, fmaf(cy, ny, cz * nz)) * 0.57735026918962576f; // /sqrt(3)
        float f[CH] = {cx, cy, cz, nx, ny, nz, pos};
        float h[CH];
#pragma unroll
        for (int o = 0; o < CH; ++o) {
            float acc = 0.f;
#pragma unroll
            for (int c = 0; c < CH; ++c) acc = fmaf(f[c], w1s[o * CH + c], acc);
            h[o] = acc;
            vals[o] += acc;
            vals[CH + o] = fmaf(acc, acc, vals[CH + o]);
        }
        const int r = p * KNB + j;
        g_h[2*r]     = make_float4(h[0], h[1], h[2], h[3]);
        g_h[2*r + 1] = make_float4(h[4], h[5], h[6], 0.f);
    }
    block_reduce_14(vals, g_sum1, g_sq1);
}

// ---------------- BN finalize (also re-zeroes accumulators for next replay) --------
__global__ void finalize1_kernel(const float* __restrict__ gamma, const float* __restrict__ beta) {
    int o = threadIdx.x;
    if (o < CH) {
        const float invN = 1.0f / (float)NROWS;
        float m = g_sum1[o] * invN;
        float v = g_sq1[o] * invN - m * m;
        float sc = gamma[o] * rsqrtf(v + 1e-5f);
        g_aff1[o] = sc;
        g_aff1[CH + o] = fmaf(-m, sc, beta[o]);
        g_sum1[o] = 0.f; g_sq1[o] = 0.f;
    }
}
__global__ void finalize2_kernel(const float* __restrict__ gamma, const float* __restrict__ beta) {
    int o = threadIdx.x;
    if (o < CH) {
        const float invN = 1.0f / (float)NROWS;
        float m = g_sum2[o] * invN;
        float v = g_sq2[o] * invN - m * m;
        float sc = gamma[o] * rsqrtf(v + 1e-5f);
        g_aff2[o] = sc;
        g_aff2[CH + o] = fmaf(-m, sc, beta[o]);
        g_sum2[o] = 0.f; g_sq2[o] = 0.f;
    }
}

// ---------------- kernel 4: relu(bn1) -> MLP2 (+bias) in place, BN2 stats ----------
__global__ void __launch_bounds__(256) mlp2_kernel(const float* __restrict__ w2,
                                                   const float* __restrict__ bias2) {
    __shared__ float w2s[CH * CH], cb[CH], aff[2 * CH];
    const int t = threadIdx.x;
    if (t < CH * CH) w2s[t] = w2[t];
    if (t < CH)      cb[t]  = bias2[t];
    if (t < 2 * CH)  aff[t] = g_aff1[t];
    __syncthreads();

    const int r = blockIdx.x * 256 + t;    // < NROWS (exact)
    float4 h0 = g_h[2*r], h1 = g_h[2*r + 1];
    float hv[CH] = {h0.x, h0.y, h0.z, h0.w, h1.x, h1.y, h1.z};
    float a[CH];
#pragma unroll
    for (int c = 0; c < CH; ++c) a[c] = fmaxf(fmaf(hv[c], aff[c], aff[CH + c]), 0.f);
    float vals[2 * CH];
#pragma unroll
    for (int o = 0; o < CH; ++o) {
        float acc = cb[o];
#pragma unroll
        for (int c = 0; c < CH; ++c) acc = fmaf(a[c], w2s[o * CH + c], acc);
        vals[o] = acc;
        vals[CH + o] = acc * acc;
    }
    g_h[2*r]     = make_float4(vals[0], vals[1], vals[2], vals[3]);
    g_h[2*r + 1] = make_float4(vals[4], vals[5], vals[6], 0.f);
    block_reduce_14(vals, g_sum2, g_sq2);
}

// ---------------- kernel 6: relu(bn2) -> MLP3 (+bias) -> max over K -> concat -------
__global__ void __launch_bounds__(256) out_kernel(const float* __restrict__ x,
                                                  const float* __restrict__ w3,
                                                  const float* __restrict__ bias3,
                                                  float* __restrict__ out) {
    __shared__ float w3s[CH * CH], cb[CH], aff[2 * CH];
    const int t = threadIdx.x;
    if (t < CH * CH) w3s[t] = w3[t];
    if (t < CH)      cb[t]  = bias3[t];
    if (t < 2 * CH)  aff[t] = g_aff2[t];
    __syncthreads();

    const int p = blockIdx.x * 256 + t;    // point id
    float best[CH];
#pragma unroll
    for (int o = 0; o < CH; ++o) best[o] = -INF_F;

#pragma unroll
    for (int j = 0; j < KNB; ++j) {
        const int r = p * KNB + j;
        float4 h0 = g_h[2*r], h1 = g_h[2*r + 1];
        float hv[CH] = {h0.x, h0.y, h0.z, h0.w, h1.x, h1.y, h1.z};
        float a[CH];
#pragma unroll
        for (int c = 0; c < CH; ++c) a[c] = fmaxf(fmaf(hv[c], aff[c], aff[CH + c]), 0.f);
#pragma unroll
        for (int o = 0; o < CH; ++o) {
            float acc = cb[o];
#pragma unroll
            for (int c = 0; c < CH; ++c) acc = fmaf(a[c], w3s[o * CH + c], acc);
            best[o] = fmaxf(best[o], acc);
        }
    }
    float* orow = out + p * 10;
    orow[0] = x[p*3]; orow[1] = x[p*3+1]; orow[2] = x[p*3+2];
#pragma unroll
    for (int o = 0; o < CH; ++o) orow[3 + o] = best[o];
}

// ---------------- launch ----------------
extern "C" void kernel_launch(void* const* d_in, const int* in_sizes, int n_in,
                              void* d_out, int out_size) {
    const float* x      = (const float*)d_in[0];
    const float* w1     = (const float*)d_in[1];
    const float* gamma1 = (const float*)d_in[2];
    const float* beta1  = (const float*)d_in[3];
    const float* w2     = (const float*)d_in[4];
    const float* bias2  = (const float*)d_in[5];
    const float* gamma2 = (const float*)d_in[6];
    const float* beta2  = (const float*)d_in[7];
    const float* w3     = (const float*)d_in[8];
    const float* bias3  = (const float*)d_in[9];
    float* out = (float*)d_out;

    const int knn_smem = SLICE_N * (int)sizeof(ulonglong2);   // 32 KB
    cudaFuncSetAttribute(knn_kernel, cudaFuncAttributeMaxDynamicSharedMemorySize, knn_smem);

    knn_kernel<<<dim3(NPT / 256, BATCH, SLICES), 256, knn_smem>>>(x);
    feat_kernel<<<NPTS / 256, 256>>>(x, w1);
    finalize1_kernel<<<1, 32>>>(gamma1, beta1);
    mlp2_kernel<<<NROWS / 256, 256>>>(w2, bias2);
    finalize2_kernel<<<1, 32>>>(gamma2, beta2);
    out_kernel<<<NPTS / 256, 256>>>(x, w3, bias3, out);
}

// round 8
// speedup vs baseline: 1.2937x; 1.2937x over previous
#include <cuda_runtime.h>

#define BATCH 4
#define NPT   8192
#define KNB   9
#define CH    7
#define NPTS  (BATCH*NPT)      // 32768
#define NROWS (NPTS*KNB)       // 294912
#define SLICES 2
#define SLICE_N (NPT/SLICES)   // 4096

typedef unsigned long long ull;

// ---------------- device scratch (no allocations allowed) ----------------
__device__ ull    g_q[NPTS*SLICES*KNB];     // partial top-9 as (key<<32)|idx, sorted asc
__device__ float4 g_h[NROWS*2];             // hidden activations, 8 floats/row (padded)
__device__ float  g_sum1[CH], g_sq1[CH];    // BN1 accumulators (zero-init, re-zeroed each launch)
__device__ float  g_sum2[CH], g_sq2[CH];    // BN2 accumulators
__device__ float  g_aff1[2*CH];             // [scale..., shift...]
__device__ float  g_aff2[2*CH];

#define INF_F (__int_as_float(0x7f800000))
// key for +INF distance: order(0x7f800000) = 0xFF800000
#define QINIT 0xFF80000000000000ull

__device__ __forceinline__ ull pk2(float a, float b) {
    return (ull)__float_as_uint(a) | ((ull)__float_as_uint(b) << 32);
}
__device__ __forceinline__ float2 upk2(ull v) {
    float2 r;
    r.x = __uint_as_float((unsigned)(v & 0xffffffffull));
    r.y = __uint_as_float((unsigned)(v >> 32));
    return r;
}
__device__ __forceinline__ ull fma2(ull a, ull b, ull c) {
    ull d;
    asm("fma.rn.f32x2 %0, %1, %2, %3;" : "=l"(d) : "l"(a), "l"(b), "l"(c));
    return d;
}
// monotone map float -> u32 so unsigned order == float order
__device__ __forceinline__ unsigned fkey(float f) {
    unsigned u = __float_as_uint(f);
    return u ^ ((unsigned)((int)u >> 31) | 0x80000000u);
}
__device__ __forceinline__ float fkey_inv(unsigned k) {
    unsigned u = (k & 0x80000000u) ? (k & 0x7fffffffu) : ~k;
    return __uint_as_float(u);
}
// branch-free insert of v into sorted-ascending q[KNB]; no-op if v >= q[KNB-1]
__device__ __forceinline__ void qinsert(ull* q, ull v) {
    ull hi = v;
#pragma unroll
    for (int j = 0; j < KNB; ++j) {
        ull old = q[j];
        q[j] = (hi < old) ? hi : old;
        hi   = (old > v) ? old : v;
    }
}

// ---------------- kernel 1: sliced brute-force 9-NN (branch-free top-9) -----------
__global__ void __launch_bounds__(128) knn_kernel(const float* __restrict__ x) {
    extern __shared__ ulonglong2 spk[];     // [SLICE_N] : pair p -> spk[2p]={x01,y01}, spk[2p+1]={z01,w01}
    const int b = blockIdx.y;
    const int s = blockIdx.z;
    const int sbase = s * SLICE_N;
    const float* xb = x + b * (NPT * 3);

    for (int p = threadIdx.x; p < SLICE_N / 2; p += 128) {
        const int c0 = sbase + 2 * p, c1 = c0 + 1;
        float x0 = xb[3*c0], y0 = xb[3*c0+1], z0 = xb[3*c0+2];
        float x1 = xb[3*c1], y1 = xb[3*c1+1], z1 = xb[3*c1+2];
        float w0 = fmaf(x0, x0, fmaf(y0, y0, z0 * z0));
        float w1 = fmaf(x1, x1, fmaf(y1, y1, z1 * z1));
        ulonglong2 A, B;
        A.x = pk2(x0, x1); A.y = pk2(y0, y1);
        B.x = pk2(z0, z1); B.y = pk2(w0, w1);
        spk[2*p]     = A;
        spk[2*p + 1] = B;
    }
    __syncthreads();

    const int n = blockIdx.x * 128 + threadIdx.x;   // query within batch
    const float qx = xb[3*n], qy = xb[3*n+1], qz = xb[3*n+2];
    const float ax = -2.0f * qx, ay = -2.0f * qy, az = -2.0f * qz;
    const ull axx = pk2(ax, ax), ayy = pk2(ay, ay), azz = pk2(az, az);

    ull q[KNB];
#pragma unroll
    for (int j = 0; j < KNB; ++j) q[j] = QINIT;
    float thr = INF_F;                      // 9th-smallest so far (float space)

    for (int pp = 0; pp < SLICE_N / 2; pp += 4) {       // 8 candidates per group
        ull d01[4];
#pragma unroll
        for (int i = 0; i < 4; ++i) {
            ulonglong2 A = spk[2*(pp + i)];
            ulonglong2 B = spk[2*(pp + i) + 1];
            // same FMA order as scalar: fmaf(x,ax, fmaf(y,ay, fmaf(z,az,w)))
            ull t = fma2(B.x, azz, B.y);
            t = fma2(A.y, ayy, t);
            d01[i] = fma2(A.x, axx, t);
        }
        float2 f0 = upk2(d01[0]), f1 = upk2(d01[1]), f2 = upk2(d01[2]), f3 = upk2(d01[3]);
        float gmin = fminf(fminf(fminf(f0.x, f0.y), fminf(f1.x, f1.y)),
                           fminf(fminf(f2.x, f2.y), fminf(f3.x, f3.y)));
        if (gmin <= thr) {
#pragma unroll
            for (int i = 0; i < 4; ++i) {
                float2 f = upk2(d01[i]);
#pragma unroll
                for (int h = 0; h < 2; ++h) {
                    float dd = h ? f.y : f.x;
                    int mm = sbase + 2 * (pp + i) + h;
                    if (dd <= thr && mm != n) {
                        ull v = ((ull)fkey(dd) << 32) | (unsigned)mm;
                        qinsert(q, v);                       // branch-free, keeps sort
                        thr = fkey_inv((unsigned)(q[KNB-1] >> 32));
                    }
                }
            }
        }
    }

    ull* op = g_q + ((ull)((b * NPT + n) * SLICES + s)) * KNB;
#pragma unroll
    for (int j = 0; j < KNB; ++j) op[j] = q[j];
}

// ---------------- block reduction of 14 partial sums -> global atomics ----------------
__device__ __forceinline__ void block_reduce_14(float* v, float* dst1, float* dst2) {
    __shared__ float red[8 * 14];
    const int lane = threadIdx.x & 31, w = threadIdx.x >> 5;
#pragma unroll
    for (int i = 0; i < 14; ++i) {
        float t = v[i];
        t += __shfl_down_sync(0xffffffffu, t, 16);
        t += __shfl_down_sync(0xffffffffu, t, 8);
        t += __shfl_down_sync(0xffffffffu, t, 4);
        t += __shfl_down_sync(0xffffffffu, t, 2);
        t += __shfl_down_sync(0xffffffffu, t, 1);
        v[i] = t;
    }
    if (lane == 0) {
#pragma unroll
        for (int i = 0; i < 14; ++i) red[w * 14 + i] = v[i];
    }
    __syncthreads();
    if (threadIdx.x < 14) {
        float t = 0.f;
#pragma unroll
        for (int ww = 0; ww < 8; ++ww) t += red[ww * 14 + threadIdx.x];
        if (threadIdx.x < CH) atomicAdd(&dst1[threadIdx.x], t);
        else                  atomicAdd(&dst2[threadIdx.x - CH], t);
    }
}

// ---------------- kernel 2: slice merge + features + MLP1 + BN1 stats ----------------
__global__ void __launch_bounds__(256) feat_kernel(const float* __restrict__ x,
                                                   const float* __restrict__ w1) {
    __shared__ float w1s[CH * CH];
    if (threadIdx.x < CH * CH) w1s[threadIdx.x] = w1[threadIdx.x];
    __syncthreads();

    const int p = blockIdx.x * 256 + threadIdx.x;     // 0..NPTS-1
    const int b = p >> 13;
    const int n = p & (NPT - 1);

    // --- merge the 2 sorted partial lists (branch-free inserts, static indexing) ---
    ull A[KNB];
    const ull* qp = g_q + (ull)p * SLICES * KNB;
#pragma unroll
    for (int j = 0; j < KNB; ++j) A[j] = qp[j];
#pragma unroll
    for (int j = 0; j < KNB; ++j) qinsert(A, qp[KNB + j]);

    const float* xb = x + b * (NPT * 3);
    const float qx = xb[3*n], qy = xb[3*n+1], qz = xb[3*n+2];

    float vx[KNB], vy[KNB], vz[KNB], ph[KNB];
#pragma unroll
    for (int j = 0; j < KNB; ++j) {
        int mi = (int)(unsigned)(A[j] & 0xffffffffull);
        vx[j] = xb[3*mi]   - qx;
        vy[j] = xb[3*mi+1] - qy;
        vz[j] = xb[3*mi+2] - qz;
        ph[j] = atan2f(vy[j], vx[j]);   // monotone in reference's phi
    }
    // stable unrolled insertion sort by phi ascending (registers only)
#pragma unroll
    for (int i = 1; i < KNB; ++i)
#pragma unroll
        for (int j = i; j > 0; --j)
            if (ph[j] < ph[j-1]) {
                float t;
                t = ph[j]; ph[j] = ph[j-1]; ph[j-1] = t;
                t = vx[j]; vx[j] = vx[j-1]; vx[j-1] = t;
                t = vy[j]; vy[j] = vy[j-1]; vy[j-1] = t;
                t = vz[j]; vz[j] = vz[j-1]; vz[j-1] = t;
            }

    float mask = 1.0f;
    float vals[2 * CH];
#pragma unroll
    for (int i = 0; i < 2 * CH; ++i) vals[i] = 0.f;

#pragma unroll
    for (int j = 0; j < KNB; ++j) {
        const int j2 = (j + 1 == KNB) ? 0 : (j + 1);
        float axv = vx[j],  ayv = vy[j],  azv = vz[j];
        float bxv = vx[j2], byv = vy[j2], bzv = vz[j2];
        float cx = 0.5f * (axv + bxv), cy = 0.5f * (ayv + byv), cz = 0.5f * (azv + bzv);
        float nx = fmaf(ayv, bzv, -azv * byv) + 1e-5f;
        float ny = fmaf(azv, bxv, -axv * bzv) + 1e-5f;
        float nz = fmaf(axv, byv, -ayv * bxv) + 1e-5f;
        float inv = rsqrtf(fmaf(nx, nx, fmaf(ny, ny, nz * nz)));
        nx *= inv; ny *= inv; nz *= inv;
        if (j == 0) mask = (nx > 0.f) ? 1.f : -1.f;
        nx *= mask; ny *= mask; nz *= mask;
        float pos = fmaf(cx, nx, fmaf(cy, ny, cz * nz)) * 0.57735026918962576f; // /sqrt(3)
        float f[CH] = {cx, cy, cz, nx, ny, nz, pos};
        float h[CH];
#pragma unroll
        for (int o = 0; o < CH; ++o) {
            float acc = 0.f;
#pragma unroll
            for (int c = 0; c < CH; ++c) acc = fmaf(f[c], w1s[o * CH + c], acc);
            h[o] = acc;
            vals[o] += acc;
            vals[CH + o] = fmaf(acc, acc, vals[CH + o]);
        }
        const int r = p * KNB + j;
        g_h[2*r]     = make_float4(h[0], h[1], h[2], h[3]);
        g_h[2*r + 1] = make_float4(h[4], h[5], h[6], 0.f);
    }
    block_reduce_14(vals, g_sum1, g_sq1);
}

// ---------------- BN finalize (also re-zeroes accumulators for next replay) --------
__global__ void finalize1_kernel(const float* __restrict__ gamma, const float* __restrict__ beta) {
    int o = threadIdx.x;
    if (o < CH) {
        const float invN = 1.0f / (float)NROWS;
        float m = g_sum1[o] * invN;
        float v = g_sq1[o] * invN - m * m;
        float sc = gamma[o] * rsqrtf(v + 1e-5f);
        g_aff1[o] = sc;
        g_aff1[CH + o] = fmaf(-m, sc, beta[o]);
        g_sum1[o] = 0.f; g_sq1[o] = 0.f;
    }
}
__global__ void finalize2_kernel(const float* __restrict__ gamma, const float* __restrict__ beta) {
    int o = threadIdx.x;
    if (o < CH) {
        const float invN = 1.0f / (float)NROWS;
        float m = g_sum2[o] * invN;
        float v = g_sq2[o] * invN - m * m;
        float sc = gamma[o] * rsqrtf(v + 1e-5f);
        g_aff2[o] = sc;
        g_aff2[CH + o] = fmaf(-m, sc, beta[o]);
        g_sum2[o] = 0.f; g_sq2[o] = 0.f;
    }
}

// ---------------- kernel 4: relu(bn1) -> MLP2 (+bias) in place, BN2 stats ----------
__global__ void __launch_bounds__(256) mlp2_kernel(const float* __restrict__ w2,
                                                   const float* __restrict__ bias2) {
    __shared__ float w2s[CH * CH], cb[CH], aff[2 * CH];
    const int t = threadIdx.x;
    if (t < CH * CH) w2s[t] = w2[t];
    if (t < CH)      cb[t]  = bias2[t];
    if (t < 2 * CH)  aff[t] = g_aff1[t];
    __syncthreads();

    const int r = blockIdx.x * 256 + t;    // < NROWS (exact)
    float4 h0 = g_h[2*r], h1 = g_h[2*r + 1];
    float hv[CH] = {h0.x, h0.y, h0.z, h0.w, h1.x, h1.y, h1.z};
    float a[CH];
#pragma unroll
    for (int c = 0; c < CH; ++c) a[c] = fmaxf(fmaf(hv[c], aff[c], aff[CH + c]), 0.f);
    float vals[2 * CH];
#pragma unroll
    for (int o = 0; o < CH; ++o) {
        float acc = cb[o];
#pragma unroll
        for (int c = 0; c < CH; ++c) acc = fmaf(a[c], w2s[o * CH + c], acc);
        vals[o] = acc;
        vals[CH + o] = acc * acc;
    }
    g_h[2*r]     = make_float4(vals[0], vals[1], vals[2], vals[3]);
    g_h[2*r + 1] = make_float4(vals[4], vals[5], vals[6], 0.f);
    block_reduce_14(vals, g_sum2, g_sq2);
}

// ---------------- kernel 6: relu(bn2) -> MLP3 (+bias) -> max over K -> concat -------
__global__ void __launch_bounds__(256) out_kernel(const float* __restrict__ x,
                                                  const float* __restrict__ w3,
                                                  const float* __restrict__ bias3,
                                                  float* __restrict__ out) {
    __shared__ float w3s[CH * CH], cb[CH], aff[2 * CH];
    const int t = threadIdx.x;
    if (t < CH * CH) w3s[t] = w3[t];
    if (t < CH)      cb[t]  = bias3[t];
    if (t < 2 * CH)  aff[t] = g_aff2[t];
    __syncthreads();

    const int p = blockIdx.x * 256 + t;    // point id
    float best[CH];
#pragma unroll
    for (int o = 0; o < CH; ++o) best[o] = -INF_F;

#pragma unroll
    for (int j = 0; j < KNB; ++j) {
        const int r = p * KNB + j;
        float4 h0 = g_h[2*r], h1 = g_h[2*r + 1];
        float hv[CH] = {h0.x, h0.y, h0.z, h0.w, h1.x, h1.y, h1.z};
        float a[CH];
#pragma unroll
        for (int c = 0; c < CH; ++c) a[c] = fmaxf(fmaf(hv[c], aff[c], aff[CH + c]), 0.f);
#pragma unroll
        for (int o = 0; o < CH; ++o) {
            float acc = cb[o];
#pragma unroll
            for (int c = 0; c < CH; ++c) acc = fmaf(a[c], w3s[o * CH + c], acc);
            best[o] = fmaxf(best[o], acc);
        }
    }
    float* orow = out + p * 10;
    orow[0] = x[p*3]; orow[1] = x[p*3+1]; orow[2] = x[p*3+2];
#pragma unroll
    for (int o = 0; o < CH; ++o) orow[3 + o] = best[o];
}

// ---------------- launch ----------------
extern "C" void kernel_launch(void* const* d_in, const int* in_sizes, int n_in,
                              void* d_out, int out_size) {
    const float* x      = (const float*)d_in[0];
    const float* w1     = (const float*)d_in[1];
    const float* gamma1 = (const float*)d_in[2];
    const float* beta1  = (const float*)d_in[3];
    const float* w2     = (const float*)d_in[4];
    const float* bias2  = (const float*)d_in[5];
    const float* gamma2 = (const float*)d_in[6];
    const float* beta2  = (const float*)d_in[7];
    const float* w3     = (const float*)d_in[8];
    const float* bias3  = (const float*)d_in[9];
    float* out = (float*)d_out;

    const int knn_smem = SLICE_N * (int)sizeof(ulonglong2);   // 64 KB
    cudaFuncSetAttribute(knn_kernel, cudaFuncAttributeMaxDynamicSharedMemorySize, knn_smem);

    knn_kernel<<<dim3(NPT / 128, BATCH, SLICES), 128, knn_smem>>>(x);
    feat_kernel<<<NPTS / 256, 256>>>(x, w1);
    finalize1_kernel<<<1, 32>>>(gamma1, beta1);
    mlp2_kernel<<<NROWS / 256, 256>>>(w2, bias2);
    finalize2_kernel<<<1, 32>>>(gamma2, beta2);
    out_kernel<<<NPTS / 256, 256>>>(x, w3, bias3, out);
}

// round 9
// speedup vs baseline: 2.2245x; 1.7195x over previous
#include <cuda_runtime.h>

#define BATCH 4
#define NPT   8192
#define KNB   9
#define CH    7
#define NPTS  (BATCH*NPT)      // 32768
#define NROWS (NPTS*KNB)       // 294912
#define SLICES 2
#define SLICE_N (NPT/SLICES)   // 4096

typedef unsigned long long ull;

// ---------------- device scratch (no allocations allowed) ----------------
__device__ ull    g_q[NPTS*SLICES*KNB];     // partial top-9 as (key<<32)|idx, sorted asc
__device__ float4 g_h[NROWS*2];             // hidden activations, 8 floats/row (padded)
__device__ float  g_sum1[CH], g_sq1[CH];    // BN1 accumulators (zeroed by knn block 0 each replay)
__device__ float  g_sum2[CH], g_sq2[CH];    // BN2 accumulators

#define INF_F (__int_as_float(0x7f800000))

__device__ __forceinline__ ull pk2(float a, float b) {
    return (ull)__float_as_uint(a) | ((ull)__float_as_uint(b) << 32);
}
__device__ __forceinline__ float2 upk2(ull v) {
    float2 r;
    r.x = __uint_as_float((unsigned)(v & 0xffffffffull));
    r.y = __uint_as_float((unsigned)(v >> 32));
    return r;
}
__device__ __forceinline__ ull fma2(ull a, ull b, ull c) {
    ull d;
    asm("fma.rn.f32x2 %0, %1, %2, %3;" : "=l"(d) : "l"(a), "l"(b), "l"(c));
    return d;
}
// monotone map float -> u32 so unsigned order == float order
__device__ __forceinline__ unsigned fkey(float f) {
    unsigned u = __float_as_uint(f);
    return u ^ ((unsigned)((int)u >> 31) | 0x80000000u);
}
// branch-free insert of u64 v into sorted-ascending q[KNB] (used only in slice merge)
__device__ __forceinline__ void qinsert(ull* q, ull v) {
    ull hi = v;
#pragma unroll
    for (int j = 0; j < KNB; ++j) {
        ull old = q[j];
        q[j] = (hi < old) ? hi : old;
        hi   = (old > v) ? old : v;
    }
}

// ---------------- kernel 1: sliced brute-force 9-NN ----------------
// 256 queries/block x one candidate slice; single-divergent-region branchless insert.
__global__ void __launch_bounds__(256) knn_kernel(const float* __restrict__ x) {
    extern __shared__ ulonglong2 spk[];     // [SLICE_N] pairs: spk[2p]={x01,y01}, spk[2p+1]={z01,w01}
    // zero BN accumulators for this replay (accumulation happens only in later kernels)
    if (blockIdx.x == 0 && blockIdx.y == 0 && blockIdx.z == 0 && threadIdx.x < CH) {
        g_sum1[threadIdx.x] = 0.f; g_sq1[threadIdx.x] = 0.f;
        g_sum2[threadIdx.x] = 0.f; g_sq2[threadIdx.x] = 0.f;
    }
    const int b = blockIdx.y;
    const int s = blockIdx.z;
    const int sbase = s * SLICE_N;
    const float* xb = x + b * (NPT * 3);

    for (int p = threadIdx.x; p < SLICE_N / 2; p += 256) {
        const int c0 = sbase + 2 * p, c1 = c0 + 1;
        float x0 = xb[3*c0], y0 = xb[3*c0+1], z0 = xb[3*c0+2];
        float x1 = xb[3*c1], y1 = xb[3*c1+1], z1 = xb[3*c1+2];
        float w0 = fmaf(x0, x0, fmaf(y0, y0, z0 * z0));
        float w1 = fmaf(x1, x1, fmaf(y1, y1, z1 * z1));
        ulonglong2 A, B;
        A.x = pk2(x0, x1); A.y = pk2(y0, y1);
        B.x = pk2(z0, z1); B.y = pk2(w0, w1);
        spk[2*p]     = A;
        spk[2*p + 1] = B;
    }
    __syncthreads();

    const int n = blockIdx.x * 256 + threadIdx.x;   // query within batch
    const float qx = xb[3*n], qy = xb[3*n+1], qz = xb[3*n+2];
    const float ax = -2.0f * qx, ay = -2.0f * qy, az = -2.0f * qz;
    const ull axx = pk2(ax, ax), ayy = pk2(ay, ay), azz = pk2(az, az);

    float dist[KNB]; int idn[KNB];
#pragma unroll
    for (int j = 0; j < KNB; ++j) { dist[j] = INF_F; idn[j] = 0; }
    float thr = INF_F;   // current 9th-smallest

    for (int pp = 0; pp < SLICE_N / 2; pp += 4) {       // 8 candidates per group
        ull d01[4];
#pragma unroll
        for (int i = 0; i < 4; ++i) {
            ulonglong2 A = spk[2*(pp + i)];
            ulonglong2 B = spk[2*(pp + i) + 1];
            // same FMA order as scalar: fmaf(x,ax, fmaf(y,ay, fmaf(z,az,w)))
            ull t = fma2(B.x, azz, B.y);
            t = fma2(A.y, ayy, t);
            d01[i] = fma2(A.x, axx, t);
        }
        float2 f0 = upk2(d01[0]), f1 = upk2(d01[1]), f2 = upk2(d01[2]), f3 = upk2(d01[3]);
        float gmin = fminf(fminf(fminf(f0.x, f0.y), fminf(f1.x, f1.y)),
                           fminf(fminf(f2.x, f2.y), fminf(f3.x, f3.y)));
        if (gmin < thr) {
#pragma unroll
            for (int i = 0; i < 4; ++i) {
                float2 f = upk2(d01[i]);
#pragma unroll
                for (int h = 0; h < 2; ++h) {
                    float dd = h ? f.y : f.x;
                    int mm = sbase + 2 * (pp + i) + h;
                    if (dd < thr && mm != n) {
                        // flat branchless sorted insert: one divergent region, no inner branches
                        float hd = dd; int hi = mm;
#pragma unroll
                        for (int j = 0; j < KNB; ++j) {
                            bool  c  = hd < dist[j];
                            float nd = c ? hd : dist[j];
                            int   ni = c ? hi : idn[j];
                            hd = c ? dist[j] : hd;
                            hi = c ? idn[j]  : hi;
                            dist[j] = nd; idn[j] = ni;
                        }
                        thr = dist[KNB-1];
                    }
                }
            }
        }
    }

    ull* op = g_q + ((ull)((b * NPT + n) * SLICES + s)) * KNB;
#pragma unroll
    for (int j = 0; j < KNB; ++j)
        op[j] = ((ull)fkey(dist[j]) << 32) | (unsigned)idn[j];
}

// ---------------- block reduction of 14 partial sums -> global atomics ----------------
__device__ __forceinline__ void block_reduce_14(float* v, float* dst1, float* dst2) {
    __shared__ float red[8 * 14];
    const int lane = threadIdx.x & 31, w = threadIdx.x >> 5;
#pragma unroll
    for (int i = 0; i < 14; ++i) {
        float t = v[i];
        t += __shfl_down_sync(0xffffffffu, t, 16);
        t += __shfl_down_sync(0xffffffffu, t, 8);
        t += __shfl_down_sync(0xffffffffu, t, 4);
        t += __shfl_down_sync(0xffffffffu, t, 2);
        t += __shfl_down_sync(0xffffffffu, t, 1);
        v[i] = t;
    }
    if (lane == 0) {
#pragma unroll
        for (int i = 0; i < 14; ++i) red[w * 14 + i] = v[i];
    }
    __syncthreads();
    if (threadIdx.x < 14) {
        float t = 0.f;
#pragma unroll
        for (int ww = 0; ww < 8; ++ww) t += red[ww * 14 + threadIdx.x];
        if (threadIdx.x < CH) atomicAdd(&dst1[threadIdx.x], t);
        else                  atomicAdd(&dst2[threadIdx.x - CH], t);
    }
}

// ---------------- kernel 2: slice merge + features + MLP1 + BN1 stats ----------------
__global__ void __launch_bounds__(256) feat_kernel(const float* __restrict__ x,
                                                   const float* __restrict__ w1) {
    __shared__ float w1s[CH * CH];
    if (threadIdx.x < CH * CH) w1s[threadIdx.x] = w1[threadIdx.x];
    __syncthreads();

    const int p = blockIdx.x * 256 + threadIdx.x;     // 0..NPTS-1
    const int b = p >> 13;
    const int n = p & (NPT - 1);

    // --- merge the 2 sorted partial lists (branch-free inserts, static indexing) ---
    ull A[KNB];
    const ull* qp = g_q + (ull)p * SLICES * KNB;
#pragma unroll
    for (int j = 0; j < KNB; ++j) A[j] = qp[j];
#pragma unroll
    for (int j = 0; j < KNB; ++j) qinsert(A, qp[KNB + j]);

    const float* xb = x + b * (NPT * 3);
    const float qx = xb[3*n], qy = xb[3*n+1], qz = xb[3*n+2];

    float vx[KNB], vy[KNB], vz[KNB], ph[KNB];
#pragma unroll
    for (int j = 0; j < KNB; ++j) {
        int mi = (int)(unsigned)(A[j] & 0xffffffffull);
        vx[j] = xb[3*mi]   - qx;
        vy[j] = xb[3*mi+1] - qy;
        vz[j] = xb[3*mi+2] - qz;
        ph[j] = atan2f(vy[j], vx[j]);   // monotone in reference's phi
    }
    // stable unrolled insertion sort by phi ascending (registers only)
#pragma unroll
    for (int i = 1; i < KNB; ++i)
#pragma unroll
        for (int j = i; j > 0; --j)
            if (ph[j] < ph[j-1]) {
                float t;
                t = ph[j]; ph[j] = ph[j-1]; ph[j-1] = t;
                t = vx[j]; vx[j] = vx[j-1]; vx[j-1] = t;
                t = vy[j]; vy[j] = vy[j-1]; vy[j-1] = t;
                t = vz[j]; vz[j] = vz[j-1]; vz[j-1] = t;
            }

    float mask = 1.0f;
    float vals[2 * CH];
#pragma unroll
    for (int i = 0; i < 2 * CH; ++i) vals[i] = 0.f;

#pragma unroll
    for (int j = 0; j < KNB; ++j) {
        const int j2 = (j + 1 == KNB) ? 0 : (j + 1);
        float axv = vx[j],  ayv = vy[j],  azv = vz[j];
        float bxv = vx[j2], byv = vy[j2], bzv = vz[j2];
        float cx = 0.5f * (axv + bxv), cy = 0.5f * (ayv + byv), cz = 0.5f * (azv + bzv);
        float nx = fmaf(ayv, bzv, -azv * byv) + 1e-5f;
        float ny = fmaf(azv, bxv, -axv * bzv) + 1e-5f;
        float nz = fmaf(axv, byv, -ayv * bxv) + 1e-5f;
        float inv = rsqrtf(fmaf(nx, nx, fmaf(ny, ny, nz * nz)));
        nx *= inv; ny *= inv; nz *= inv;
        if (j == 0) mask = (nx > 0.f) ? 1.f : -1.f;
        nx *= mask; ny *= mask; nz *= mask;
        float pos = fmaf(cx, nx, fmaf(cy, ny, cz * nz)) * 0.57735026918962576f; // /sqrt(3)
        float f[CH] = {cx, cy, cz, nx, ny, nz, pos};
        float h[CH];
#pragma unroll
        for (int o = 0; o < CH; ++o) {
            float acc = 0.f;
#pragma unroll
            for (int c = 0; c < CH; ++c) acc = fmaf(f[c], w1s[o * CH + c], acc);
            h[o] = acc;
            vals[o] += acc;
            vals[CH + o] = fmaf(acc, acc, vals[CH + o]);
        }
        const int r = p * KNB + j;
        g_h[2*r]     = make_float4(h[0], h[1], h[2], h[3]);
        g_h[2*r + 1] = make_float4(h[4], h[5], h[6], 0.f);
    }
    block_reduce_14(vals, g_sum1, g_sq1);
}

// ---------------- kernel 3: relu(bn1) -> MLP2 (+bias) in place, BN2 stats ----------
// BN1 affine computed inline per block from g_sum1/g_sq1 (complete after feat_kernel).
__global__ void __launch_bounds__(256) mlp2_kernel(const float* __restrict__ w2,
                                                   const float* __restrict__ bias2,
                                                   const float* __restrict__ gamma1,
                                                   const float* __restrict__ beta1) {
    __shared__ float w2s[CH * CH], cb[CH], aff[2 * CH];
    const int t = threadIdx.x;
    if (t < CH * CH) w2s[t] = w2[t];
    if (t < CH)      cb[t]  = bias2[t];
    if (t < CH) {
        const float invN = 1.0f / (float)NROWS;
        float m = g_sum1[t] * invN;
        float v = g_sq1[t] * invN - m * m;
        float sc = gamma1[t] * rsqrtf(v + 1e-5f);
        aff[t] = sc;
        aff[CH + t] = fmaf(-m, sc, beta1[t]);
    }
    __syncthreads();

    const int r = blockIdx.x * 256 + t;    // < NROWS (exact)
    float4 h0 = g_h[2*r], h1 = g_h[2*r + 1];
    float hv[CH] = {h0.x, h0.y, h0.z, h0.w, h1.x, h1.y, h1.z};
    float a[CH];
#pragma unroll
    for (int c = 0; c < CH; ++c) a[c] = fmaxf(fmaf(hv[c], aff[c], aff[CH + c]), 0.f);
    float vals[2 * CH];
#pragma unroll
    for (int o = 0; o < CH; ++o) {
        float acc = cb[o];
#pragma unroll
        for (int c = 0; c < CH; ++c) acc = fmaf(a[c], w2s[o * CH + c], acc);
        vals[o] = acc;
        vals[CH + o] = acc * acc;
    }
    g_h[2*r]     = make_float4(vals[0], vals[1], vals[2], vals[3]);
    g_h[2*r + 1] = make_float4(vals[4], vals[5], vals[6], 0.f);
    block_reduce_14(vals, g_sum2, g_sq2);
}

// ---------------- kernel 4: relu(bn2) -> MLP3 (+bias) -> max over K -> concat -------
// BN2 affine computed inline per block from g_sum2/g_sq2 (complete after mlp2_kernel).
__global__ void __launch_bounds__(256) out_kernel(const float* __restrict__ x,
                                                  const float* __restrict__ w3,
                                                  const float* __restrict__ bias3,
                                                  const float* __restrict__ gamma2,
                                                  const float* __restrict__ beta2,
                                                  float* __restrict__ out) {
    __shared__ float w3s[CH * CH], cb[CH], aff[2 * CH];
    const int t = threadIdx.x;
    if (t < CH * CH) w3s[t] = w3[t];
    if (t < CH)      cb[t]  = bias3[t];
    if (t < CH) {
        const float invN = 1.0f / (float)NROWS;
        float m = g_sum2[t] * invN;
        float v = g_sq2[t] * invN - m * m;
        float sc = gamma2[t] * rsqrtf(v + 1e-5f);
        aff[t] = sc;
        aff[CH + t] = fmaf(-m, sc, beta2[t]);
    }
    __syncthreads();

    const int p = blockIdx.x * 256 + t;    // point id
    float best[CH];
#pragma unroll
    for (int o = 0; o < CH; ++o) best[o] = -INF_F;

#pragma unroll
    for (int j = 0; j < KNB; ++j) {
        const int r = p * KNB + j;
        float4 h0 = g_h[2*r], h1 = g_h[2*r + 1];
        float hv[CH] = {h0.x, h0.y, h0.z, h0.w, h1.x, h1.y, h1.z};
        float a[CH];
#pragma unroll
        for (int c = 0; c < CH; ++c) a[c] = fmaxf(fmaf(hv[c], aff[c], aff[CH + c]), 0.f);
#pragma unroll
        for (int o = 0; o < CH; ++o) {
            float acc = cb[o];
#pragma unroll
            for (int c = 0; c < CH; ++c) acc = fmaf(a[c], w3s[o * CH + c], acc);
            best[o] = fmaxf(best[o], acc);
        }
    }
    float* orow = out + p * 10;
    orow[0] = x[p*3]; orow[1] = x[p*3+1]; orow[2] = x[p*3+2];
#pragma unroll
    for (int o = 0; o < CH; ++o) orow[3 + o] = best[o];
}

// ---------------- launch ----------------
extern "C" void kernel_launch(void* const* d_in, const int* in_sizes, int n_in,
                              void* d_out, int out_size) {
    const float* x      = (const float*)d_in[0];
    const float* w1     = (const float*)d_in[1];
    const float* gamma1 = (const float*)d_in[2];
    const float* beta1  = (const float*)d_in[3];
    const float* w2     = (const float*)d_in[4];
    const float* bias2  = (const float*)d_in[5];
    const float* gamma2 = (const float*)d_in[6];
    const float* beta2  = (const float*)d_in[7];
    const float* w3     = (const float*)d_in[8];
    const float* bias3  = (const float*)d_in[9];
    float* out = (float*)d_out;

    const int knn_smem = SLICE_N * (int)sizeof(ulonglong2);   // 64 KB
    cudaFuncSetAttribute(knn_kernel, cudaFuncAttributeMaxDynamicSharedMemorySize, knn_smem);

    knn_kernel<<<dim3(NPT / 256, BATCH, SLICES), 256, knn_smem>>>(x);
    feat_kernel<<<NPTS / 256, 256>>>(x, w1);
    mlp2_kernel<<<NROWS / 256, 256>>>(w2, bias2, gamma1, beta1);
    out_kernel<<<NPTS / 256, 256>>>(x, w3, bias3, gamma2, beta2, out);
}

// round 10
// speedup vs baseline: 2.2590x; 1.0155x over previous
#include <cuda_runtime.h>

#define BATCH 4
#define NPT   8192
#define KNB   9
#define CH    7
#define NPTS  (BATCH*NPT)      // 32768
#define NROWS (NPTS*KNB)       // 294912
#define SLICES 2
#define SLICE_N (NPT/SLICES)   // 4096
#define LOGCAP 128             // per (query,slice) insert log capacity (E=64, 8 sigma margin)

typedef unsigned long long ull;

// ---------------- device scratch (no allocations allowed) ----------------
__device__ float2 g_log[(size_t)NPTS*SLICES*LOGCAP]; // insert log: (dist, idx-bits)
__device__ int    g_lcnt[NPTS*SLICES];               // log counts
__device__ float  g_pd[NPTS*SLICES*KNB];             // per-slice top-9 distances (sorted asc)
__device__ float4 g_h[NROWS*2];                      // hidden activations, 8 floats/row
__device__ float  g_sum1[CH], g_sq1[CH];             // BN1 accumulators
__device__ float  g_sum2[CH], g_sq2[CH];             // BN2 accumulators

#define INF_F (__int_as_float(0x7f800000))

__device__ __forceinline__ ull pk2(float a, float b) {
    return (ull)__float_as_uint(a) | ((ull)__float_as_uint(b) << 32);
}
__device__ __forceinline__ float2 upk2(ull v) {
    float2 r;
    r.x = __uint_as_float((unsigned)(v & 0xffffffffull));
    r.y = __uint_as_float((unsigned)(v >> 32));
    return r;
}
__device__ __forceinline__ ull fma2(ull a, ull b, ull c) {
    ull d;
    asm("fma.rn.f32x2 %0, %1, %2, %3;" : "=l"(d) : "l"(a), "l"(b), "l"(c));
    return d;
}
// insert d into sorted-ascending dist[KNB], popping the max; pure FMNMX chain
__device__ __forceinline__ void dchain(float* dist, float d) {
    float hd = d;
#pragma unroll
    for (int j = 0; j < KNB; ++j) {
        float lo = fminf(hd, dist[j]);
        hd = fmaxf(hd, dist[j]);
        dist[j] = lo;
    }
}

// ---------------- kernel 1: sliced brute-force 9-NN (distance chain + index log) ----
__global__ void __launch_bounds__(256) knn_kernel(const float* __restrict__ x) {
    extern __shared__ ulonglong2 spk[];     // [SLICE_N] pairs: spk[2p]={x01,y01}, spk[2p+1]={z01,w01}
    if (blockIdx.x == 0 && blockIdx.y == 0 && blockIdx.z == 0 && threadIdx.x < CH) {
        g_sum1[threadIdx.x] = 0.f; g_sq1[threadIdx.x] = 0.f;
        g_sum2[threadIdx.x] = 0.f; g_sq2[threadIdx.x] = 0.f;
    }
    const int b = blockIdx.y;
    const int s = blockIdx.z;
    const int sbase = s * SLICE_N;
    const float* xb = x + b * (NPT * 3);

    for (int p = threadIdx.x; p < SLICE_N / 2; p += 256) {
        const int c0 = sbase + 2 * p, c1 = c0 + 1;
        float x0 = xb[3*c0], y0 = xb[3*c0+1], z0 = xb[3*c0+2];
        float x1 = xb[3*c1], y1 = xb[3*c1+1], z1 = xb[3*c1+2];
        float w0 = fmaf(x0, x0, fmaf(y0, y0, z0 * z0));
        float w1 = fmaf(x1, x1, fmaf(y1, y1, z1 * z1));
        ulonglong2 A, B;
        A.x = pk2(x0, x1); A.y = pk2(y0, y1);
        B.x = pk2(z0, z1); B.y = pk2(w0, w1);
        spk[2*p]     = A;
        spk[2*p + 1] = B;
    }
    __syncthreads();

    const int n = blockIdx.x * 256 + threadIdx.x;   // query within batch
    const float qx = xb[3*n], qy = xb[3*n+1], qz = xb[3*n+2];
    const float ax = -2.0f * qx, ay = -2.0f * qy, az = -2.0f * qz;
    const ull axx = pk2(ax, ax), ayy = pk2(ay, ay), azz = pk2(az, az);

    float dist[KNB];
#pragma unroll
    for (int j = 0; j < KNB; ++j) dist[j] = INF_F;
    float thr = INF_F;
    int cnt = 0;
    float2* lg = g_log + (size_t)((b * NPT + n) * SLICES + s) * LOGCAP;

    for (int pp = 0; pp < SLICE_N / 2; pp += 4) {       // 8 candidates per group
        ull d01[4];
#pragma unroll
        for (int i = 0; i < 4; ++i) {
            ulonglong2 A = spk[2*(pp + i)];
            ulonglong2 B = spk[2*(pp + i) + 1];
            ull t = fma2(B.x, azz, B.y);
            t = fma2(A.y, ayy, t);
            d01[i] = fma2(A.x, axx, t);
        }
        float2 f0 = upk2(d01[0]), f1 = upk2(d01[1]), f2 = upk2(d01[2]), f3 = upk2(d01[3]);
        float gmin = fminf(fminf(fminf(f0.x, f0.y), fminf(f1.x, f1.y)),
                           fminf(fminf(f2.x, f2.y), fminf(f3.x, f3.y)));
        if (gmin < thr) {
#pragma unroll
            for (int i = 0; i < 4; ++i) {
                float2 f = upk2(d01[i]);
#pragma unroll
                for (int h = 0; h < 2; ++h) {
                    float dd = h ? f.y : f.x;
                    int mm = sbase + 2 * (pp + i) + h;
                    if (dd < thr && mm != n) {
                        int w = (cnt < LOGCAP) ? cnt : (LOGCAP - 1);
                        lg[w] = make_float2(dd, __int_as_float(mm));
                        ++cnt;
                        dchain(dist, dd);          // 18 FMNMX, no idx tracking
                        thr = dist[KNB-1];
                    }
                }
            }
        }
    }

    const int q = (b * NPT + n) * SLICES + s;
    g_lcnt[q] = (cnt < LOGCAP) ? cnt : LOGCAP;
#pragma unroll
    for (int j = 0; j < KNB; ++j) g_pd[q * KNB + j] = dist[j];
}

// ---------------- block reduction of 14 partial sums -> global atomics ----------------
__device__ __forceinline__ void block_reduce_14(float* v, float* dst1, float* dst2) {
    __shared__ float red[8 * 14];
    const int lane = threadIdx.x & 31, w = threadIdx.x >> 5;
#pragma unroll
    for (int i = 0; i < 14; ++i) {
        float t = v[i];
        t += __shfl_down_sync(0xffffffffu, t, 16);
        t += __shfl_down_sync(0xffffffffu, t, 8);
        t += __shfl_down_sync(0xffffffffu, t, 4);
        t += __shfl_down_sync(0xffffffffu, t, 2);
        t += __shfl_down_sync(0xffffffffu, t, 1);
        v[i] = t;
    }
    if (lane == 0) {
#pragma unroll
        for (int i = 0; i < 14; ++i) red[w * 14 + i] = v[i];
    }
    __syncthreads();
    if (threadIdx.x < 14) {
        float t = 0.f;
#pragma unroll
        for (int ww = 0; ww < 8; ++ww) t += red[ww * 14 + threadIdx.x];
        if (threadIdx.x < CH) atomicAdd(&dst1[threadIdx.x], t);
        else                  atomicAdd(&dst2[threadIdx.x - CH], t);
    }
}

// ---------------- kernel 2: merge + index claim + features + MLP1 + BN1 stats --------
__global__ void __launch_bounds__(256) feat_kernel(const float* __restrict__ x,
                                                   const float* __restrict__ w1) {
    __shared__ float w1s[CH * CH];
    if (threadIdx.x < CH * CH) w1s[threadIdx.x] = w1[threadIdx.x];
    __syncthreads();

    const int p = blockIdx.x * 256 + threadIdx.x;     // 0..NPTS-1
    const int b = p >> 13;
    const int n = p & (NPT - 1);

    // --- merge the two sorted per-slice top-9 distance lists ---
    float dm[KNB];
#pragma unroll
    for (int j = 0; j < KNB; ++j) dm[j] = g_pd[(p * SLICES) * KNB + j];
#pragma unroll
    for (int j = 0; j < KNB; ++j) dchain(dm, g_pd[(p * SLICES + 1) * KNB + j]);

    // --- claim indices by scanning logs in candidate-index order ---
    // log order within a slice = scan order = ascending index; slice0 indices < slice1.
    // Leftmost-unclaimed-equal matching == top_k's lower-index-first tie-break.
    int idx[KNB];
    unsigned claimed = 0;
    const float dmax = dm[KNB-1];
    const float2* lgq = g_log + (size_t)p * SLICES * LOGCAP;
#pragma unroll
    for (int s2 = 0; s2 < SLICES; ++s2) {
        const float2* L = lgq + (size_t)s2 * LOGCAP;
        const int cn = g_lcnt[p * SLICES + s2];
        for (int k = 0; k < cn; ++k) {
            float2 e = L[k];
            if (e.x <= dmax) {
                bool done = false;
#pragma unroll
                for (int j = 0; j < KNB; ++j) {
                    bool m = (!done) && (dm[j] == e.x) && !((claimed >> j) & 1u);
                    if (m) { idx[j] = __float_as_int(e.y); claimed |= (1u << j); done = true; }
                }
            }
        }
    }

    const float* xb = x + b * (NPT * 3);
    const float qx = xb[3*n], qy = xb[3*n+1], qz = xb[3*n+2];

    float vx[KNB], vy[KNB], vz[KNB], ph[KNB];
#pragma unroll
    for (int j = 0; j < KNB; ++j) {
        int mi = idx[j];
        vx[j] = xb[3*mi]   - qx;
        vy[j] = xb[3*mi+1] - qy;
        vz[j] = xb[3*mi+2] - qz;
        ph[j] = atan2f(vy[j], vx[j]);   // monotone in reference's phi
    }
    // stable unrolled insertion sort by phi ascending (registers only)
#pragma unroll
    for (int i = 1; i < KNB; ++i)
#pragma unroll
        for (int j = i; j > 0; --j)
            if (ph[j] < ph[j-1]) {
                float t;
                t = ph[j]; ph[j] = ph[j-1]; ph[j-1] = t;
                t = vx[j]; vx[j] = vx[j-1]; vx[j-1] = t;
                t = vy[j]; vy[j] = vy[j-1]; vy[j-1] = t;
                t = vz[j]; vz[j] = vz[j-1]; vz[j-1] = t;
            }

    float mask = 1.0f;
    float vals[2 * CH];
#pragma unroll
    for (int i = 0; i < 2 * CH; ++i) vals[i] = 0.f;

#pragma unroll
    for (int j = 0; j < KNB; ++j) {
        const int j2 = (j + 1 == KNB) ? 0 : (j + 1);
        float axv = vx[j],  ayv = vy[j],  azv = vz[j];
        float bxv = vx[j2], byv = vy[j2], bzv = vz[j2];
        float cx = 0.5f * (axv + bxv), cy = 0.5f * (ayv + byv), cz = 0.5f * (azv + bzv);
        float nx = fmaf(ayv, bzv, -azv * byv) + 1e-5f;
        float ny = fmaf(azv, bxv, -axv * bzv) + 1e-5f;
        float nz = fmaf(axv, byv, -ayv * bxv) + 1e-5f;
        float inv = rsqrtf(fmaf(nx, nx, fmaf(ny, ny, nz * nz)));
        nx *= inv; ny *= inv; nz *= inv;
        if (j == 0) mask = (nx > 0.f) ? 1.f : -1.f;
        nx *= mask; ny *= mask; nz *= mask;
        float pos = fmaf(cx, nx, fmaf(cy, ny, cz * nz)) * 0.57735026918962576f; // /sqrt(3)
        float f[CH] = {cx, cy, cz, nx, ny, nz, pos};
        float h[CH];
#pragma unroll
        for (int o = 0; o < CH; ++o) {
            float acc = 0.f;
#pragma unroll
            for (int c = 0; c < CH; ++c) acc = fmaf(f[c], w1s[o * CH + c], acc);
            h[o] = acc;
            vals[o] += acc;
            vals[CH + o] = fmaf(acc, acc, vals[CH + o]);
        }
        const int r = p * KNB + j;
        g_h[2*r]     = make_float4(h[0], h[1], h[2], h[3]);
        g_h[2*r + 1] = make_float4(h[4], h[5], h[6], 0.f);
    }
    block_reduce_14(vals, g_sum1, g_sq1);
}

// ---------------- kernel 3: relu(bn1) -> MLP2 (+bias) in place, BN2 stats ----------
__global__ void __launch_bounds__(256) mlp2_kernel(const float* __restrict__ w2,
                                                   const float* __restrict__ bias2,
                                                   const float* __restrict__ gamma1,
                                                   const float* __restrict__ beta1) {
    __shared__ float w2s[CH * CH], cb[CH], aff[2 * CH];
    const int t = threadIdx.x;
    if (t < CH * CH) w2s[t] = w2[t];
    if (t < CH)      cb[t]  = bias2[t];
    if (t < CH) {
        const float invN = 1.0f / (float)NROWS;
        float m = g_sum1[t] * invN;
        float v = g_sq1[t] * invN - m * m;
        float sc = gamma1[t] * rsqrtf(v + 1e-5f);
        aff[t] = sc;
        aff[CH + t] = fmaf(-m, sc, beta1[t]);
    }
    __syncthreads();

    const int r = blockIdx.x * 256 + t;    // < NROWS (exact)
    float4 h0 = g_h[2*r], h1 = g_h[2*r + 1];
    float hv[CH] = {h0.x, h0.y, h0.z, h0.w, h1.x, h1.y, h1.z};
    float a[CH];
#pragma unroll
    for (int c = 0; c < CH; ++c) a[c] = fmaxf(fmaf(hv[c], aff[c], aff[CH + c]), 0.f);
    float vals[2 * CH];
#pragma unroll
    for (int o = 0; o < CH; ++o) {
        float acc = cb[o];
#pragma unroll
        for (int c = 0; c < CH; ++c) acc = fmaf(a[c], w2s[o * CH + c], acc);
        vals[o] = acc;
        vals[CH + o] = acc * acc;
    }
    g_h[2*r]     = make_float4(vals[0], vals[1], vals[2], vals[3]);
    g_h[2*r + 1] = make_float4(vals[4], vals[5], vals[6], 0.f);
    block_reduce_14(vals, g_sum2, g_sq2);
}

// ---------------- kernel 4: relu(bn2) -> MLP3 (+bias) -> max over K -> concat -------
__global__ void __launch_bounds__(256) out_kernel(const float* __restrict__ x,
                                                  const float* __restrict__ w3,
                                                  const float* __restrict__ bias3,
                                                  const float* __restrict__ gamma2,
                                                  const float* __restrict__ beta2,
                                                  float* __restrict__ out) {
    __shared__ float w3s[CH * CH], cb[CH], aff[2 * CH];
    const int t = threadIdx.x;
    if (t < CH * CH) w3s[t] = w3[t];
    if (t < CH)      cb[t]  = bias3[t];
    if (t < CH) {
        const float invN = 1.0f / (float)NROWS;
        float m = g_sum2[t] * invN;
        float v = g_sq2[t] * invN - m * m;
        float sc = gamma2[t] * rsqrtf(v + 1e-5f);
        aff[t] = sc;
        aff[CH + t] = fmaf(-m, sc, beta2[t]);
    }
    __syncthreads();

    const int p = blockIdx.x * 256 + t;    // point id
    float best[CH];
#pragma unroll
    for (int o = 0; o < CH; ++o) best[o] = -INF_F;

#pragma unroll
    for (int j = 0; j < KNB; ++j) {
        const int r = p * KNB + j;
        float4 h0 = g_h[2*r], h1 = g_h[2*r + 1];
        float hv[CH] = {h0.x, h0.y, h0.z, h0.w, h1.x, h1.y, h1.z};
        float a[CH];
#pragma unroll
        for (int c = 0; c < CH; ++c) a[c] = fmaxf(fmaf(hv[c], aff[c], aff[CH + c]), 0.f);
#pragma unroll
        for (int o = 0; o < CH; ++o) {
            float acc = cb[o];
#pragma unroll
            for (int c = 0; c < CH; ++c) acc = fmaf(a[c], w3s[o * CH + c], acc);
            best[o] = fmaxf(best[o], acc);
        }
    }
    float* orow = out + p * 10;
    orow[0] = x[p*3]; orow[1] = x[p*3+1]; orow[2] = x[p*3+2];
#pragma unroll
    for (int o = 0; o < CH; ++o) orow[3 + o] = best[o];
}

// ---------------- launch ----------------
extern "C" void kernel_launch(void* const* d_in, const int* in_sizes, int n_in,
                              void* d_out, int out_size) {
    const float* x      = (const float*)d_in[0];
    const float* w1     = (const float*)d_in[1];
    const float* gamma1 = (const float*)d_in[2];
    const float* beta1  = (const float*)d_in[3];
    const float* w2     = (const float*)d_in[4];
    const float* bias2  = (const float*)d_in[5];
    const float* gamma2 = (const float*)d_in[6];
    const float* beta2  = (const float*)d_in[7];
    const float* w3     = (const float*)d_in[8];
    const float* bias3  = (const float*)d_in[9];
    float* out = (float*)d_out;

    const int knn_smem = SLICE_N * (int)sizeof(ulonglong2);   // 64 KB
    cudaFuncSetAttribute(knn_kernel, cudaFuncAttributeMaxDynamicSharedMemorySize, knn_smem);

    knn_kernel<<<dim3(NPT / 256, BATCH, SLICES), 256, knn_smem>>>(x);
    feat_kernel<<<NPTS / 256, 256>>>(x, w1);
    mlp2_kernel<<<NROWS / 256, 256>>>(w2, bias2, gamma1, beta1);
    out_kernel<<<NPTS / 256, 256>>>(x, w3, bias3, gamma2, beta2, out);
}